// round 17
// baseline (speedup 1.0000x reference)
#include <cuda_runtime.h>
#include <cuda_fp16.h>
#include <cstdint>
#include <math.h>

#define Bb 2
#define Ll 1024
#define Dd 512
#define Hh 8
#define hh 64
#define EPSF 1e-5f

// ---------------- scratch (device globals; no runtime allocation) ----------------
__device__ __half g_xh[2048*512];
__device__ __half g_wqkvT[1536*512];
__device__ __half g_woT[512*512];
__device__ __half g_ktr[16*64*1024];
__device__ __half g_vtr[16*64*1024];
__device__ __half g_uh[2048*512];
// Toeplitz tiles (64x64, padded LDK): [head][didx 0..15], diff = didx*64
#define LDK 72
#define TOEP_SZ (64*LDK)
__device__ __half g_toep[8*16*TOEP_SZ];
__device__ float g_q [16*1024*64];
__device__ float g_kc[16*1024*64];
__device__ float g_vc[16*1024*64];
__device__ float g_gate[16*1024];
__device__ float g_Spart[16*16*64*64];

// ---------------- helpers ----------------
__device__ __forceinline__ uint32_t smem_u32(const void* p){
    uint32_t a;
    asm("{ .reg .u64 t; cvta.to.shared.u64 t, %1; cvt.u32.u64 %0, t; }" : "=r"(a) : "l"(p));
    return a;
}

#define LDSM_X4(d0,d1,d2,d3,addr) \
    asm volatile("ldmatrix.sync.aligned.m8n8.x4.shared.b16 {%0,%1,%2,%3}, [%4];" \
        : "=r"(d0),"=r"(d1),"=r"(d2),"=r"(d3) : "r"(addr))

__device__ __forceinline__ void mma_f16(float* c, const uint32_t* a, uint32_t b0, uint32_t b1){
    asm volatile(
        "mma.sync.aligned.m16n8k16.row.col.f32.f16.f16.f32 "
        "{%0,%1,%2,%3},{%4,%5,%6,%7},{%8,%9},{%0,%1,%2,%3};"
        : "+f"(c[0]),"+f"(c[1]),"+f"(c[2]),"+f"(c[3])
        : "r"(a[0]),"r"(a[1]),"r"(a[2]),"r"(a[3]),"r"(b0),"r"(b1));
}

__device__ __forceinline__ void cp16(uint32_t dst, const void* src){
    asm volatile("cp.async.ca.shared.global [%0], [%1], 16;" :: "r"(dst), "l"(src));
}
#define CP_COMMIT() asm volatile("cp.async.commit_group;" ::: "memory")
#define CP_WAIT1()  asm volatile("cp.async.wait_group 1;" ::: "memory")
#define CP_WAIT0()  asm volatile("cp.async.wait_group 0;" ::: "memory")

// K64 stage geometry: rows padded to LDK=72 fp16 (144B)
#define PTILE_B (128*LDK*2)        // 18432: one 128x64 tile
#define PSTG_B  (2*PTILE_B)        // 36864: A | B
#define CAT_B   (64*LDK*2)         // 9216:  conv A tile 64x64
#define CBT_B   (128*LDK*2)        // 18432: conv B tile 128x64
#define CSTG_B  (CAT_B+CBT_B)      // 27648

// one K64 chunk, warp tile 32x64 (8 warps over 128x128). acc[2][8][4].
__device__ __forceinline__ void mma_chunk(
    uint32_t A, uint32_t B, int warpM, int warpN, int lane, float acc[2][8][4])
{
    const int rsub = ((lane >> 3) & 1) * 8 + (lane & 7);
    const int ksel = (lane >> 4) * 8;
    #pragma unroll
    for (int ks = 0; ks < 64; ks += 16){
        uint32_t ah[2][4], bh[4][4];
        #pragma unroll
        for (int mt = 0; mt < 2; mt++){
            uint32_t off = ((warpM*32 + mt*16 + rsub) * LDK + ks + ksel) * 2;
            LDSM_X4(ah[mt][0],ah[mt][1],ah[mt][2],ah[mt][3], A + off);
        }
        #pragma unroll
        for (int np = 0; np < 4; np++){
            uint32_t off = ((warpN*64 + np*16 + rsub) * LDK + ks + ksel) * 2;
            LDSM_X4(bh[np][0],bh[np][1],bh[np][2],bh[np][3], B + off);
        }
        #pragma unroll
        for (int mt = 0; mt < 2; mt++)
            #pragma unroll
            for (int nt = 0; nt < 8; nt++){
                int np = nt >> 1, s = nt & 1;
                mma_f16(acc[mt][nt], ah[mt], bh[np][s], bh[np][s+2]);
            }
    }
}

// conv: one K64 chunk, warp tile 32x32 (8 warps over 64x128). acc[2][4][4].
__device__ __forceinline__ void mma_chunk64(
    uint32_t A, uint32_t B, int warpM, int warpN, int lane, float acc[2][4][4])
{
    const int rsub = ((lane >> 3) & 1) * 8 + (lane & 7);
    const int ksel = (lane >> 4) * 8;
    #pragma unroll
    for (int ks = 0; ks < 64; ks += 16){
        uint32_t ah[2][4], bh[2][4];
        #pragma unroll
        for (int mt = 0; mt < 2; mt++){
            uint32_t off = ((warpM*32 + mt*16 + rsub) * LDK + ks + ksel) * 2;
            LDSM_X4(ah[mt][0],ah[mt][1],ah[mt][2],ah[mt][3], A + off);
        }
        #pragma unroll
        for (int np = 0; np < 2; np++){
            uint32_t off = ((warpN*32 + np*16 + rsub) * LDK + ks + ksel) * 2;
            LDSM_X4(bh[np][0],bh[np][1],bh[np][2],bh[np][3], B + off);
        }
        #pragma unroll
        for (int mt = 0; mt < 2; mt++)
            #pragma unroll
            for (int nt = 0; nt < 4; nt++){
                int np = nt >> 1, s = nt & 1;
                mma_f16(acc[mt][nt], ah[mt], bh[np][s], bh[np][s+2]);
            }
    }
}

// async-load one 128x64 fp16 tile (row-major, stride elems), 256 threads, 4 cp16 each
__device__ __forceinline__ void load_tile_128x64(uint32_t dst, const __half* src, int stride, int tid){
    #pragma unroll
    for (int j = 0; j < 4; j++){
        int i = tid + j * 256;
        int r = i >> 3, seg = (i & 7) * 8;
        cp16(dst + (r * LDK + seg) * 2, src + (long)r * stride + seg);
    }
}

// =====================================================================
// P: fused prep
// =====================================================================
__global__ __launch_bounds__(256) void prep_all(
    const float* __restrict__ x,
    const float* __restrict__ wq, const float* __restrict__ wk,
    const float* __restrict__ wv, const float* __restrict__ wo,
    const float* __restrict__ sbasis)
{
    const int bid = blockIdx.x;
    const int tid = threadIdx.x;

    if (bid < 1024){
        int i = bid * 256 + tid;
        float4 v = ((const float4*)x)[i];
        ((__half2*)g_xh)[i*2+0] = __floats2half2_rn(v.x, v.y);
        ((__half2*)g_xh)[i*2+1] = __floats2half2_rn(v.z, v.w);
        return;
    }
    if (bid < 1280){
        __shared__ float s[64][65];
        int idx = bid - 1024;
        int bx = idx & 31;
        int k0 = (idx >> 5) * 64;
        const float* W; __half* Dst; int n0; int dstRow0;
        if (bx < 24) {
            int ng0 = bx * 64; int mat = ng0 >> 9;
            W = (mat == 0) ? wq : (mat == 1) ? wk : wv;
            n0 = ng0 & 511; dstRow0 = ng0;
            Dst = g_wqkvT;
        } else {
            W = wo; n0 = (bx - 24) * 64; dstRow0 = n0;
            Dst = g_woT;
        }
        #pragma unroll
        for (int i = 0; i < 4; i++){
            int r = i * 16 + (tid >> 4);
            int c = (tid & 15) * 4;
            float4 v = *(const float4*)(W + (k0 + r) * 512 + n0 + c);
            s[r][c+0]=v.x; s[r][c+1]=v.y; s[r][c+2]=v.z; s[r][c+3]=v.w;
        }
        __syncthreads();
        #pragma unroll
        for (int i = 0; i < 4; i++){
            int rn = i * 16 + (tid >> 4);
            int ck = (tid & 15) * 4;
            int off = (dstRow0 + rn) * 512 + k0 + ck;
            *(__half2*)(Dst + off)     = __floats2half2_rn(s[ck+0][rn], s[ck+1][rn]);
            *(__half2*)(Dst + off + 2) = __floats2half2_rn(s[ck+2][rn], s[ck+3][rn]);
        }
        return;
    }
    {
        int idx = bid - 1280;
        int didx = idx & 15;
        int head = idx >> 4;
        int diff = didx * 64;
        __half* th = g_toep + (head * 16 + didx) * TOEP_SZ;
        for (int i = tid; i < 64 * 64; i += 256){
            int r = i >> 6, cc = i & 63;
            int lag = diff + r - cc;
            float v = (lag >= 0 && lag < 1024) ? sbasis[lag * 8 + head] : 0.0f;
            th[r * LDK + cc] = __float2half(v);
        }
    }
}

// =====================================================================
// K1: QKV projection GEMM — fp16, 8 warps, K64 2-stage.
// =====================================================================
__global__ __launch_bounds__(256) void proj_mma(
    const float* __restrict__ bq, const float* __restrict__ bk, const float* __restrict__ bv)
{
    extern __shared__ char sm[];
    const uint32_t sb = smem_u32(sm);
    const int tid = threadIdx.x;
    const int lane = tid & 31, wid = tid >> 5;
    const int warpM = wid & 3, warpN = wid >> 2;
    const int row0 = blockIdx.y * 128;
    const int n0   = blockIdx.x * 128;

    float acc[2][8][4] = {};

    auto issue = [&](int c){
        uint32_t tb = sb + (c & 1) * PSTG_B;
        int k0 = c * 64;
        load_tile_128x64(tb,           g_xh    + (long)row0*512 + k0, 512, tid);
        load_tile_128x64(tb + PTILE_B, g_wqkvT + (long)n0 *512 + k0, 512, tid);
        CP_COMMIT();
    };

    issue(0);
    for (int c = 0; c < 8; c++){
        if (c + 1 < 8){ issue(c + 1); CP_WAIT1(); } else { CP_WAIT0(); }
        __syncthreads();
        uint32_t o = sb + (c & 1) * PSTG_B;
        mma_chunk(o, o + PTILE_B, warpM, warpN, lane, acc);
        __syncthreads();
    }

    const int g   = lane >> 2;
    const int tig = lane & 3;
    const int nwarp = n0 + warpN * 64;
    const int mat  = nwarp >> 9;
    const int head = (nwarp >> 6) & 7;
    const int mrow = row0 + warpM * 32;

    if (mat == 0){
        #pragma unroll
        for (int mt = 0; mt < 2; mt++)
            #pragma unroll
            for (int nt = 0; nt < 8; nt++){
                int col = nt * 8 + tig * 2;
                float b0 = bq[(nwarp & 511) + col], b1 = bq[(nwarp & 511) + col + 1];
                #pragma unroll
                for (int rr = 0; rr < 2; rr++){
                    int row = mrow + mt*16 + g + rr*8;
                    int b = row >> 10, l = row & 1023;
                    float2 o; o.x = acc[mt][nt][rr*2+0] + b0; o.y = acc[mt][nt][rr*2+1] + b1;
                    *(float2*)(g_q + (((long)(b*8+head) << 10) + l) * 64 + col) = o;
                }
            }
    } else {
        const float sc = (mat == 1) ? 0.125f : 1.0f;
        const float* bias = (mat == 1) ? bk : bv;
        __half* Dst = (mat == 1) ? g_ktr : g_vtr;
        #pragma unroll
        for (int mt = 0; mt < 2; mt++)
            #pragma unroll
            for (int nt = 0; nt < 8; nt++){
                int col = nt * 8 + tig * 2;
                float b0 = bias[(nwarp & 511) + col], b1 = bias[(nwarp & 511) + col + 1];
                #pragma unroll
                for (int rr = 0; rr < 2; rr++){
                    int row = mrow + mt*16 + g + rr*8;
                    int b = row >> 10, l = row & 1023;
                    int bh = b * 8 + head;
                    float v0 = (acc[mt][nt][rr*2+0] + b0) * sc;
                    float v1 = (acc[mt][nt][rr*2+1] + b1) * sc;
                    long i0 = (((long)bh*64 + col)   << 10) + l;
                    long i1 = (((long)bh*64 + col+1) << 10) + l;
                    Dst[i0] = __float2half(v0);
                    Dst[i1] = __float2half(v1);
                }
            }
    }
}

// =====================================================================
// K2: conv GEMM + FUSED gate (smem-ring reuse). Balanced pairs, K64 2-stage.
// =====================================================================
__global__ __launch_bounds__(256) void conv_mma(
    const float* __restrict__ wg, const float* __restrict__ wgb)
{
    extern __shared__ char sm[];
    __shared__ float Wg[64][68];          // static, 17408 B
    const uint32_t sb = smem_u32(sm);
    float* ksm = (float*)sm;              // reuses dead ring after mainloop
    float* vsm = (float*)(sm + 17408);
    const int tid = threadIdx.x;
    const int lane = tid & 31, wid = tid >> 5;
    const int warpM = wid & 1, warpN = wid >> 1;
    const int pair = blockIdx.x;     // 0..7
    const int bh   = blockIdx.y;     // 0..15
    const int head = bh & 7;
    const float wgb0 = wgb[0];

    for (int i = tid; i < 4096; i += 256) Wg[i >> 6][i & 63] = wg[i];

    const __half* kh = g_ktr + (long)bh * 64 * 1024;
    const __half* vh = g_vtr + (long)bh * 64 * 1024;

    #pragma unroll 1
    for (int s = 0; s < 2; s++){
        const int tile = s ? (15 - pair) : pair;
        const int L0 = tile * 64;
        const int NC = tile + 1;

        float acc[2][4][4] = {};

        auto issue = [&](int c){
            uint32_t tb = sb + (c & 1) * CSTG_B;
            int T0 = c * 64;
            int didx = tile - c;
            const __half* th = g_toep + (head * 16 + didx) * TOEP_SZ;
            #pragma unroll
            for (int j = 0; j < 2; j++){
                int i = tid + j * 256;
                int r = i >> 3, seg = (i & 7) * 8;
                cp16(tb + (r * LDK + seg) * 2, th + r * LDK + seg);
            }
            #pragma unroll
            for (int j = 0; j < 4; j++){
                int i = tid + j * 256;
                int r = i >> 3, seg = (i & 7) * 8;
                const __half* sh = (r < 64) ? kh + ((long)r << 10) : vh + ((long)(r - 64) << 10);
                cp16(tb + CAT_B + (r * LDK + seg) * 2, sh + T0 + seg);
            }
            CP_COMMIT();
        };

        issue(0);
        for (int c = 0; c < NC; c++){
            if (c + 1 < NC){ issue(c + 1); CP_WAIT1(); } else { CP_WAIT0(); }
            __syncthreads();
            uint32_t o = sb + (c & 1) * CSTG_B;
            mma_chunk64(o, o + CAT_B, warpM, warpN, lane, acc);
            __syncthreads();
        }

        const int g = lane >> 2, tig = lane & 3;
        #pragma unroll
        for (int mt = 0; mt < 2; mt++)
            #pragma unroll
            for (int nt = 0; nt < 4; nt++){
                int n = warpN * 32 + nt * 8 + tig * 2;
                float* Dst = (n < 64) ? g_kc : g_vc;
                float* Smm = (n < 64) ? ksm : vsm;
                int col = n & 63;
                #pragma unroll
                for (int rr = 0; rr < 2; rr++){
                    int ll = warpM*32 + mt*16 + g + rr*8;
                    float2 o; o.x = acc[mt][nt][rr*2+0]; o.y = acc[mt][nt][rr*2+1];
                    *(float2*)(Dst + (((long)bh << 10) + L0 + ll) * 64 + col) = o;
                    *(float2*)(Smm + ll * 68 + col) = o;
                }
            }
        __syncthreads();

        // fused gate: 4 threads per l, mod-4 m-interleave (conflict-free)
        {
            const int ll2 = tid >> 2;
            const int q   = tid & 3;
            float kreg[64];
            #pragma unroll
            for (int n = 0; n < 16; n++){
                float4 a = *(const float4*)&ksm[ll2 * 68 + n * 4];
                kreg[n*4+0]=a.x; kreg[n*4+1]=a.y; kreg[n*4+2]=a.z; kreg[n*4+3]=a.w;
            }
            float acc2 = 0.0f;
            #pragma unroll 2
            for (int mp = 0; mp < 16; mp++){
                int m = 4*mp + q;
                float vm = vsm[ll2 * 68 + m];
                float dot = 0.0f;
                #pragma unroll
                for (int n4 = 0; n4 < 16; n4++){
                    float4 w4 = *(const float4*)&Wg[m][n4 * 4];
                    dot += w4.x * kreg[n4*4+0];
                    dot += w4.y * kreg[n4*4+1];
                    dot += w4.z * kreg[n4*4+2];
                    dot += w4.w * kreg[n4*4+3];
                }
                acc2 += vm * dot;
            }
            acc2 += __shfl_down_sync(0xffffffffu, acc2, 2, 4);
            acc2 += __shfl_down_sync(0xffffffffu, acc2, 1, 4);
            if (q == 0){
                float a = acc2 + wgb0;
                float rl = fmaxf(a, 0.0f);
                g_gate[(bh << 10) + L0 + ll2] = rl * rl + EPSF;
            }
        }
        __syncthreads();
    }
}

// =====================================================================
// block scan helper (256 threads, 1024 elems)
// =====================================================================
__device__ __forceinline__ void block_scan_1024(float* arr, float* wsum)
{
    const int tid = threadIdx.x;
    const int lane = tid & 31, wid = tid >> 5;
    float v0 = arr[tid*4+0], v1 = arr[tid*4+1], v2 = arr[tid*4+2], v3 = arr[tid*4+3];
    v1 += v0; v2 += v1; v3 += v2;
    float s = v3;
    #pragma unroll
    for (int o = 1; o < 32; o <<= 1) {
        float t = __shfl_up_sync(0xffffffff, s, o);
        if (lane >= o) s += t;
    }
    float excl = s - v3;
    if (lane == 31) wsum[wid] = s;
    __syncthreads();
    if (wid == 0) {
        float ws = (lane < 8) ? wsum[lane] : 0.0f;
        #pragma unroll
        for (int o = 1; o < 8; o <<= 1) {
            float t = __shfl_up_sync(0xffffffff, ws, o);
            if (lane >= o) ws += t;
        }
        if (lane < 8) wsum[lane] = ws;
    }
    __syncthreads();
    float base = ((wid > 0) ? wsum[wid - 1] : 0.0f) + excl;
    arr[tid*4+0] = v0 + base; arr[tid*4+1] = v1 + base;
    arr[tid*4+2] = v2 + base; arr[tid*4+3] = v3 + base;
    __syncthreads();
}

// =====================================================================
// K5: S partials, 16 t-chunks of 64, fused scan per block.
// =====================================================================
__global__ __launch_bounds__(256) void Spart_kernel()
{
    __shared__ float Vs[64][68];
    __shared__ float Ks[64][68];
    __shared__ float gg[1024];
    __shared__ float pp[1024];
    __shared__ float rr[1024];
    __shared__ float ws[8];
    const int tc = blockIdx.x, bh = blockIdx.y;
    const float* vin = g_vc + (long)bh * Ll * hh;
    const float* kin = g_kc + (long)bh * Ll * hh;
    const int tid = threadIdx.x;
    const int tx = tid & 15, ty = tid >> 4;

    {
        const float* gin = g_gate + bh * 1024;
        for (int i = tid; i < 1024; i += 256){ float v = gin[i]; gg[i] = v; pp[i] = v; }
        __syncthreads();
        block_scan_1024(pp, ws);                    // pp = cumG
        for (int i = tid; i < 1024; i += 256) rr[i] = 1.0f / (pp[i] + EPSF);
        __syncthreads();
        for (int i = tid; i < 1024; i += 256) pp[i] = rr[i];
        __syncthreads();
        block_scan_1024(pp, ws);                    // pp = prefix of r
    }
    const float total = pp[1023];

    float acc[4][4] = {};

    const int T0 = tc * 64;
    {
        for (int i = tid; i < 64 * 16; i += 256) {
            int rrow = i >> 4, c = (i & 15) << 2;
            int t = T0 + rrow;
            float w = gg[t] * (total - pp[t] + rr[t]);
            float4 vv = *(const float4*)(vin + (long)t * 64 + c);
            vv.x *= w; vv.y *= w; vv.z *= w; vv.w *= w;
            *(float4*)&Vs[rrow][c] = vv;
            *(float4*)&Ks[rrow][c] = *(const float4*)(kin + (long)t * 64 + c);
        }
        __syncthreads();
        #pragma unroll 4
        for (int tt = 0; tt < 64; tt++) {
            float4 a4 = *(const float4*)&Vs[tt][ty * 4];
            float4 b4 = *(const float4*)&Ks[tt][tx * 4];
            float aa[4] = {a4.x, a4.y, a4.z, a4.w};
            float bb[4] = {b4.x, b4.y, b4.z, b4.w};
            #pragma unroll
            for (int i = 0; i < 4; i++)
                #pragma unroll
                for (int j = 0; j < 4; j++)
                    acc[i][j] += aa[i] * bb[j];
        }
        __syncthreads();
    }
    float* dst = g_Spart + (tc * 16 + bh) * 4096;
    #pragma unroll
    for (int i = 0; i < 4; i++)
        #pragma unroll
        for (int j = 0; j < 4; j++)
            dst[(ty * 4 + i) * 64 + tx * 4 + j] = acc[i][j];
}

// =====================================================================
// K6: ctxt = q @ S, normalize, write fp16 unit [token][512]
// =====================================================================
__global__ __launch_bounds__(256) void ctxt_kernel()
{
    __shared__ float Ss[64][65];
    const int b = blockIdx.z, head = blockIdx.y, lc = blockIdx.x;
    const int bh = b * Hh + head;
    const int tid = threadIdx.x;
    for (int i = tid; i < 4096; i += 256) {
        float s = 0.0f;
        #pragma unroll
        for (int p = 0; p < 16; p++) s += g_Spart[(p * 16 + bh) * 4096 + i];
        Ss[i >> 6][i & 63] = s;
    }
    __syncthreads();
    const int l = lc * 256 + tid;
    const float* qrow = g_q + ((long)bh * Ll + l) * hh;
    float out[64];
    #pragma unroll
    for (int e = 0; e < 64; e++) out[e] = 0.0f;
    for (int d = 0; d < 64; d++) {
        float qd = qrow[d];
        #pragma unroll
        for (int e = 0; e < 64; e++) out[e] += qd * Ss[d][e];
    }
    float nrm = 0.0f;
    #pragma unroll
    for (int e = 0; e < 64; e++) nrm += out[e] * out[e];
    float inv = 1.0f / fmaxf(sqrtf(nrm), EPSF);
    long off = ((long)(b * 1024 + l)) * 512 + head * 64;
    #pragma unroll
    for (int e = 0; e < 64; e += 2)
        *(__half2*)(g_uh + off + e) = __floats2half2_rn(out[e] * inv, out[e+1] * inv);
}

// =====================================================================
// K7: output projection GEMM — fp16, 8 warps, K64 2-stage.
// =====================================================================
__global__ __launch_bounds__(256) void out_mma(
    const float* __restrict__ bo, float* __restrict__ out)
{
    extern __shared__ char sm[];
    const uint32_t sb = smem_u32(sm);
    const int tid = threadIdx.x;
    const int lane = tid & 31, wid = tid >> 5;
    const int warpM = wid & 3, warpN = wid >> 2;
    const int row0 = blockIdx.y * 128;
    const int n0   = blockIdx.x * 128;

    float acc[2][8][4] = {};

    auto issue = [&](int c){
        uint32_t tb = sb + (c & 1) * PSTG_B;
        int k0 = c * 64;
        load_tile_128x64(tb,           g_uh  + (long)row0*512 + k0, 512, tid);
        load_tile_128x64(tb + PTILE_B, g_woT + (long)n0 *512 + k0, 512, tid);
        CP_COMMIT();
    };

    issue(0);
    for (int c = 0; c < 8; c++){
        if (c + 1 < 8){ issue(c + 1); CP_WAIT1(); } else { CP_WAIT0(); }
        __syncthreads();
        uint32_t o = sb + (c & 1) * PSTG_B;
        mma_chunk(o, o + PTILE_B, warpM, warpN, lane, acc);
        __syncthreads();
    }

    const int g = lane >> 2, tig = lane & 3;
    #pragma unroll
    for (int mt = 0; mt < 2; mt++)
        #pragma unroll
        for (int nt = 0; nt < 8; nt++){
            int col = n0 + warpN*64 + nt*8 + tig*2;
            float b0 = bo[col], b1 = bo[col+1];
            #pragma unroll
            for (int rr = 0; rr < 2; rr++){
                int row = row0 + warpM*32 + mt*16 + g + rr*8;
                float2 o; o.x = acc[mt][nt][rr*2+0] + b0; o.y = acc[mt][nt][rr*2+1] + b1;
                *(float2*)(out + (long)row * 512 + col) = o;
            }
        }
}

// =====================================================================
extern "C" void kernel_launch(void* const* d_in, const int* in_sizes, int n_in,
                              void* d_out, int out_size)
{
    const float* x   = (const float*)d_in[0];
    const float* sb  = (const float*)d_in[1];
    const float* wq  = (const float*)d_in[2];
    const float* bq  = (const float*)d_in[3];
    const float* wk  = (const float*)d_in[4];
    const float* bk  = (const float*)d_in[5];
    const float* wv  = (const float*)d_in[6];
    const float* bv  = (const float*)d_in[7];
    const float* wo  = (const float*)d_in[8];
    const float* bo  = (const float*)d_in[9];
    const float* wg  = (const float*)d_in[10];
    const float* wgb = (const float*)d_in[11];
    float* out = (float*)d_out;

    const int GEMM_SMEM = 2 * PSTG_B;     // 73728
    const int CONV_SMEM = 2 * CSTG_B;     // 55296 dynamic (+17408 static Wg)

    cudaFuncSetAttribute(proj_mma, cudaFuncAttributeMaxDynamicSharedMemorySize, GEMM_SMEM);
    cudaFuncSetAttribute(conv_mma, cudaFuncAttributeMaxDynamicSharedMemorySize, CONV_SMEM);
    cudaFuncSetAttribute(out_mma,  cudaFuncAttributeMaxDynamicSharedMemorySize, GEMM_SMEM);

    prep_all<<<1408, 256>>>(x, wq, wk, wv, wo, sb);
    proj_mma<<<dim3(12, 16), 256, GEMM_SMEM>>>(bq, bk, bv);
    conv_mma<<<dim3(8, 16), 256, CONV_SMEM>>>(wg, wgb);
    Spart_kernel<<<dim3(16, 16), 256>>>();
    ctxt_kernel<<<dim3(4, 8, 2), 256>>>();
    out_mma<<<dim3(4, 16), 256, GEMM_SMEM>>>(bo, out);
}